// round 13
// baseline (speedup 1.0000x reference)
#include <cuda_runtime.h>
#include <cuda_bf16.h>

// Problem constants: B=32, Cin=11, H=W=128, K=8, P=7, TN=16, ED=64, SD=32
// out: (32, 64, 128, 128) float32

// ---------------- static device scratch ----------------
__device__ __align__(256) float g_TW[12 * 9 * 64];        // tap weights per class (11 = pad = 0)
__device__ __align__(256) float g_AT[64 * 64];            // AT[k][o], A = (I+W1)@conv2_w
__device__ __align__(256) float g_D[8 * 8 * 64];          // D[hm*8+wm][o]
__device__ __align__(256) float g_Fs[10 * 10 * 12 * 64];  // [ht][wt][cc][o]
__device__ __align__(256) float g_Fr[10 * 12 * 12 * 64];  // ht==8: [wt][cc][cb][o]
__device__ __align__(256) float g_Fc[10 * 12 * 12 * 64];  // wt==8: [ht][cc][cr][o]
__device__ __align__(256) float g_corner[32 * 225 * 64];  // [b][ti][tj][o]
__device__ int   g_lab[32 * 16 * 16];

// row kinds per position type t (0..9): 0=PAD,1=ZERO,2=CUR,3=NEXT
__constant__ int c_rk[10][3] = {
    {0,2,2},{1,2,2},{2,2,2},{2,2,2},{2,2,2},{2,2,2},{2,2,2},{2,2,1},{2,1,3},{2,1,0}
};

__device__ __forceinline__ int cellcls(int rk, int ck, int cc, int cr, int cb, int cd) {
    if (rk == 0 || ck == 0) return 11;
    if (rk == 1 || ck == 1) return 0;
    if (rk == 2) return (ck == 2) ? cc : cr;
    return (ck == 2) ? cb : cd;
}
__device__ __forceinline__ int hm_of(int t) { return (t <= 1) ? 0 : ((t <= 7) ? t - 1 : 7); }

// ================= K1: setup (AT / D / TW) + labels, one launch =================
// blocks 0..15: AT | 16..31: D (+prolog) | 32..58: TW | 59..90: labels
__global__ __launch_bounds__(256) void k1_kernel(
    const float* __restrict__ x,
    const float* __restrict__ c1w, const float* __restrict__ c1b,
    const float* __restrict__ c2w, const float* __restrict__ c2b,
    const float* __restrict__ sew, const float* __restrict__ seb,
    const float* __restrict__ slw, const float* __restrict__ slb,
    const float* __restrict__ rpw, const float* __restrict__ rpb,
    const float* __restrict__ fw,  const float* __restrict__ fb)
{
    __shared__ __align__(16) float smem[9600];
    int tid = threadIdx.x;
    int blk = blockIdx.x;

    if (blk < 16) {
        // ---- AT[k][o] = conv2_w[o][k] + sum_m fus_w[o][m]*conv2_w[m][k] ----
        float* sc2w = smem;          // 4096
        float* sfw4 = smem + 4096;   // 512: 4 fw rows
        int o0 = blk * 4;
        {
            const float4* src = (const float4*)c2w;
            float4* dst = (float4*)sc2w;
            #pragma unroll
            for (int i = 0; i < 4; i++) dst[i * 256 + tid] = src[i * 256 + tid];
            if (tid < 128) ((float4*)sfw4)[tid] = ((const float4*)(fw + o0 * 128))[tid];
        }
        __syncthreads();
        int ol = tid >> 6, k = tid & 63;
        int o = o0 + ol;
        float a0 = sc2w[o * 64 + k], a1 = 0.f, a2 = 0.f, a3 = 0.f;
        #pragma unroll
        for (int m = 0; m < 64; m += 4) {
            a0 += sfw4[ol * 128 + m + 0] * sc2w[(m + 0) * 64 + k];
            a1 += sfw4[ol * 128 + m + 1] * sc2w[(m + 1) * 64 + k];
            a2 += sfw4[ol * 128 + m + 2] * sc2w[(m + 2) * 64 + k];
            a3 += sfw4[ol * 128 + m + 3] * sc2w[(m + 3) * 64 + k];
        }
        g_AT[k * 64 + o] = (a0 + a1) + (a2 + a3);
    } else if (blk < 32) {
        // ---- D with staged fw (pitch 129) + parallel prolog ----
        float* sfw  = smem;                 // 8256
        float* sh_h = smem + 8256;          // 784
        float* sh_p = sh_h + 784;           // 256
        float* sh_sv = sh_p + 256;          // 32
        float* sc2b = sh_sv + 32;           // 64
        float* srpb = sc2b + 64;            // 32
        float* srpw = srpb + 32;            // 64

        {
            const float4* fw4 = (const float4*)fw;
            #pragma unroll
            for (int it = 0; it < 8; it++) {
                int f = it * 256 + tid;
                float4 v = fw4[f];
                int o = f >> 5, j4 = (f & 31) * 4;
                float* d = sfw + o * 129 + j4;
                d[0] = v.x; d[1] = v.y; d[2] = v.z; d[3] = v.w;
            }
        }
        for (int idx = tid; idx < 784; idx += 256) {
            int c = idx / 49, r = (idx % 49) / 7, j = idx % 7;
            float v = seb[c];
            #pragma unroll
            for (int ky = 0; ky < 3; ky++)
                #pragma unroll
                for (int kx = 0; kx < 3; kx++) {
                    int rr = r - 1 + ky, ccol = j - 1 + kx;
                    if (rr >= 0 && rr < 7 && ccol >= 0 && ccol < 7) v += sew[c * 9 + ky * 3 + kx];
                }
            sh_h[idx] = fmaxf(v, 0.f);
        }
        if (tid < 64) sc2b[tid] = c2b[tid];
        if (tid < 32) srpb[tid] = rpb[tid];
        if (tid < 64) srpw[tid] = rpw[tid];
        __syncthreads();
        {   // adaptive maxpool 7->4
            int c = tid / 16, ri = (tid % 16) / 4, rj = tid % 4;
            const int s4[4] = {0, 1, 3, 5}, e4[4] = {2, 4, 6, 7};
            float m = -1e30f;
            for (int r = s4[ri]; r < e4[ri]; r++)
                for (int cc = s4[rj]; cc < e4[rj]; cc++)
                    m = fmaxf(m, sh_h[c * 49 + r * 7 + cc]);
            sh_p[tid] = m;
        }
        __syncthreads();
        {   // shape_vec: warp w handles rows s = 4w..4w+3
            int warp = tid >> 5, lane = tid & 31;
            const float4* p4 = (const float4*)sh_p;
            float4 pa = p4[lane], pb = p4[lane + 32];
            #pragma unroll
            for (int si = 0; si < 4; si++) {
                int s = warp * 4 + si;
                const float4* row = (const float4*)(slw + s * 256);
                float4 ra = row[lane], rb = row[lane + 32];
                float part = ra.x * pa.x + ra.y * pa.y + ra.z * pa.z + ra.w * pa.w
                           + rb.x * pb.x + rb.y * pb.y + rb.z * pb.z + rb.w * pb.w;
                #pragma unroll
                for (int off = 16; off > 0; off >>= 1)
                    part += __shfl_down_sync(0xffffffffu, part, off);
                if (lane == 0) sh_sv[s] = fmaxf(part + slb[s], 0.f);
            }
        }
        __syncthreads();
        int p = (blk - 16) * 256 + tid;  // < 4096
        int hw = p >> 6, o = p & 63, hm = hw >> 3, wm = hw & 7;
        float d0 = sc2b[o] + fb[o], d1 = 0.f, d2 = 0.f, d3 = 0.f;
        #pragma unroll
        for (int m = 0; m < 64; m += 4) {
            d0 += sfw[o * 129 + m + 0] * sc2b[m + 0];
            d1 += sfw[o * 129 + m + 1] * sc2b[m + 1];
            d2 += sfw[o * 129 + m + 2] * sc2b[m + 2];
            d3 += sfw[o * 129 + m + 3] * sc2b[m + 3];
        }
        if (hm < 7 && wm < 7) {
            float fi = hm * (1.0f / 6.0f), fj = wm * (1.0f / 6.0f);
            #pragma unroll
            for (int s = 0; s < 32; s += 2) {
                d0 += sfw[o * 129 + 64 + s] * sh_sv[s];
                d1 += sfw[o * 129 + 65 + s] * sh_sv[s + 1];
            }
            #pragma unroll
            for (int s = 0; s < 32; s += 2) {
                d2 += sfw[o * 129 + 96 + s] * (srpb[s] + srpw[2 * s] * fi + srpw[2 * s + 1] * fj);
                d3 += sfw[o * 129 + 97 + s] * (srpb[s + 1] + srpw[2 * s + 2] * fi + srpw[2 * s + 3] * fj);
            }
        }
        g_D[hw * 64 + o] = (d0 + d1) + (d2 + d3);
    } else if (blk < 59) {
        // ---- TW[class][tap][o] ----
        int idx = (blk - 32) * 256 + tid;
        if (idx < 12 * 9 * 64) {
            int c = idx / (9 * 64), t = (idx / 64) % 9, o = idx & 63;
            g_TW[idx] = (c < 11) ? c1w[o * 99 + c * 9 + t] : 0.f;
        }
    } else {
        // ---- labels: argmax over 11 one-hot channels at tile origin ----
        int idx = (blk - 59) * 256 + tid;  // < 8192
        int b = idx >> 8, ty = (idx >> 4) & 15, tx = idx & 15;
        const float* px = x + (long long)b * 11 * 16384 + (ty * 8) * 128 + (tx * 8);
        float v[11];
        #pragma unroll
        for (int c = 0; c < 11; c++) v[c] = px[(long long)c * 16384];
        int best = 0; float bv = v[0];
        #pragma unroll
        for (int c = 1; c < 11; c++) { if (v[c] > bv) { bv = v[c]; best = c; } }
        g_lab[idx] = best;
    }
}

// ================= K2: tables + corners — register-tiled matvec =================
// Each block owns 64 entries, processed as 4 iterations of 16.
// Phase 1 (thread = (q = tid>>6, o = tid&63)): y-vectors for entries q*4+j into
//   sy[le][o]; publishes dst pointer + D-row via shared.
// Phase 2 (thread = (ee = tid>>4, o4 = (tid&15)*4)): per k ONE LDS.128 of sAT +
//   ONE broadcast LDS of sy -> 4 FMA; coalesced float4 store.
// blocks 0..55: table entries (3564 of 3584) | 56..168: corners (7200 of 7232)
__global__ __launch_bounds__(256) void k2_kernel(const float* __restrict__ c1b) {
    __shared__ float sAT[64 * 64];
    __shared__ float sy[16][64];
    __shared__ float* sdstp[16];
    __shared__ int sdhw[16];
    int tid = threadIdx.x;
    {
        const float4* src = (const float4*)g_AT;
        float4* dst4 = (float4*)sAT;
        #pragma unroll
        for (int i = 0; i < 4; i++) dst4[i * 256 + tid] = src[i * 256 + tid];
    }
    __syncthreads();

    int q = tid >> 6, o = tid & 63;
    float bias = c1b[o];
    bool isTab = blockIdx.x < 56;
    int base = isTab ? blockIdx.x * 64 : (blockIdx.x - 56) * 64;
    int lim = isTab ? 3564 : 7200;

    int ee = tid >> 4;           // phase-2 entry 0..15
    int eo4 = (tid & 15) * 4;    // phase-2 o-group

    #pragma unroll 1
    for (int it = 0; it < 4; it++) {
        // ---- phase 1 ----
        #pragma unroll
        for (int j = 0; j < 4; j++) {
            int le = q * 4 + j;
            int e = base + it * 16 + le;
            if (e < lim) {
                int ht, wt, cc, cr = 11, cb = 11, cd = 11;
                float* dstp;
                if (isTab) {
                    if (e < 972) {
                        cc = e % 12; int r = e / 12;
                        int wi = r % 9, hi = r / 9;
                        wt = (wi == 8) ? 9 : wi;
                        ht = (hi == 8) ? 9 : hi;
                        dstp = &g_Fs[((ht * 10 + wt) * 12 + cc) * 64];
                    } else if (e < 972 + 1296) {
                        int r = e - 972;
                        cb = r % 12; r /= 12; cc = r % 12;
                        int wi = r / 12; wt = (wi == 8) ? 9 : wi; ht = 8;
                        dstp = &g_Fr[((wt * 12 + cc) * 12 + cb) * 64];
                    } else {
                        int r = e - 972 - 1296;
                        cr = r % 12; r /= 12; cc = r % 12;
                        int hi = r / 12; ht = (hi == 8) ? 9 : hi; wt = 8;
                        dstp = &g_Fc[((ht * 12 + cc) * 12 + cr) * 64];
                    }
                } else {
                    int r = e % 225, ti = r / 15, tj = r % 15;
                    int labbase = ((e / 225) << 8) + (ti << 4) + tj;
                    cc = g_lab[labbase]; cr = g_lab[labbase + 1];
                    cb = g_lab[labbase + 16]; cd = g_lab[labbase + 17];
                    ht = 8; wt = 8;
                    dstp = &g_corner[e * 64];
                }
                float y = bias;
                #pragma unroll
                for (int dy = 0; dy < 3; dy++)
                    #pragma unroll
                    for (int dx = 0; dx < 3; dx++) {
                        int rk = c_rk[ht][dy], ck = c_rk[wt][dx];
                        int cls = cellcls(rk, ck, cc, cr, cb, cd);
                        y += g_TW[(cls * 9 + dy * 3 + dx) * 64 + o];
                    }
                sy[le][o] = fmaxf(y, 0.f);
                if (o == 0) {
                    sdstp[le] = dstp;
                    sdhw[le] = hm_of(ht) * 8 + hm_of(wt);
                }
            } else if (o == 0) {
                sdstp[le] = nullptr;
            }
        }
        __syncthreads();
        // ---- phase 2: register-tiled matvec (1 LDS.128 + 1 broadcast LDS -> 4 FMA) ----
        float* dp = sdstp[ee];
        if (dp != nullptr) {
            float4 acc = *(const float4*)&g_D[sdhw[ee] * 64 + eo4];
            const float* yrow = sy[ee];
            float a0 = acc.x, a1 = acc.y, a2 = acc.z, a3 = acc.w;
            #pragma unroll
            for (int k = 0; k < 64; k++) {
                float4 at = *(const float4*)&sAT[k * 64 + eo4];
                float yv = yrow[k];
                a0 += at.x * yv;
                a1 += at.y * yv;
                a2 += at.z * yv;
                a3 += at.w * yv;
            }
            float4 r4;
            r4.x = a0; r4.y = a1; r4.z = a2; r4.w = a3;
            *(float4*)&dp[eo4] = r4;
        }
        __syncthreads();
    }
}

// ================= K3: main — 8-lane gather (full-line LDG), pitch-129 transpose =================
// block = one (b,h) image row; 256 threads; 4 passes of 32 pixels.
// Warp = 4 pixels x 8 lanes: lane l8 loads F[l8] and F[l8+8] (two full 128B lines / 4 px).
__global__ __launch_bounds__(256) void main_kernel(float* __restrict__ out) {
    __shared__ float s[64 * 129];   // [ch][w], pitch 129 (odd -> conflict-free)
    int tid = threadIdx.x;
    int bh = blockIdx.x;
    int b = bh >> 7, h = bh & 127;
    int hm = h & 7;
    int ht = (hm == 0) ? (h == 0 ? 0 : 1) : (hm < 7 ? hm + 1 : (h == 127 ? 9 : 8));
    int ty = h >> 3;
    int labrow = (b << 8) + (ty << 4);
    int px32 = tid >> 3;        // 0..31: pixel within pass
    int l8 = tid & 7;           // lane within pixel
    int ch = 4 * l8;

    #pragma unroll
    for (int pass = 0; pass < 4; pass++) {
        int w = pass * 32 + px32;
        int wm = w & 7;
        int wt = (wm == 0) ? (w == 0 ? 0 : 1) : (wm < 7 ? wm + 1 : (w == 127 ? 9 : 8));
        int tx = w >> 3;
        int cc = g_lab[labrow + tx];
        const float4* F;
        if (ht == 8) {      // uniform per block
            if (wt == 8) {
                F = (const float4*)&g_corner[((b * 15 + ty) * 15 + tx) * 64];
            } else {
                int cb = g_lab[labrow + tx + 16];
                F = (const float4*)&g_Fr[((wt * 12 + cc) * 12 + cb) * 64];
            }
        } else {
            if (wt == 8) {
                int cr = g_lab[labrow + tx + 1];
                F = (const float4*)&g_Fc[((ht * 12 + cc) * 12 + cr) * 64];
            } else {
                F = (const float4*)&g_Fs[((ht * 10 + wt) * 12 + cc) * 64];
            }
        }
        float4 va = F[l8];       // line A of row
        float4 vb = F[l8 + 8];   // line B of row
        s[(ch + 0) * 129 + w] = va.x;
        s[(ch + 1) * 129 + w] = va.y;
        s[(ch + 2) * 129 + w] = va.z;
        s[(ch + 3) * 129 + w] = va.w;
        s[(ch + 32) * 129 + w] = vb.x;
        s[(ch + 33) * 129 + w] = vb.y;
        s[(ch + 34) * 129 + w] = vb.z;
        s[(ch + 35) * 129 + w] = vb.w;
    }
    __syncthreads();

    // store: idx = it*256 + tid -> c = idx>>7, w = idx&127; warp = 32 consecutive w of one c
    float* obase = out + ((long long)b << 20) + h * 128;
    #pragma unroll
    for (int it = 0; it < 32; it++) {
        int idx = it * 256 + tid;
        int c = idx >> 7, w = idx & 127;
        obase[c * 16384 + w] = s[c * 129 + w];
    }
}

// ---------------- launch ----------------
extern "C" void kernel_launch(void* const* d_in, const int* in_sizes, int n_in,
                              void* d_out, int out_size) {
    const float* x   = (const float*)d_in[0];
    const float* c1w = (const float*)d_in[1];
    const float* c1b = (const float*)d_in[2];
    const float* c2w = (const float*)d_in[3];
    const float* c2b = (const float*)d_in[4];
    const float* sew = (const float*)d_in[5];
    const float* seb = (const float*)d_in[6];
    const float* slw = (const float*)d_in[7];
    const float* slb = (const float*)d_in[8];
    const float* rpw = (const float*)d_in[9];
    const float* rpb = (const float*)d_in[10];
    const float* fus_w = (const float*)d_in[11];
    const float* fus_b = (const float*)d_in[12];
    float* out = (float*)d_out;

    k1_kernel<<<91, 256>>>(x, c1w, c1b, c2w, c2b, sew, seb, slw, slb, rpw, rpb, fus_w, fus_b);
    k2_kernel<<<169, 256>>>(c1b);
    main_kernel<<<4096, 256>>>(out);
}

// round 14
// speedup vs baseline: 1.1084x; 1.1084x over previous
#include <cuda_runtime.h>
#include <cuda_bf16.h>

// Problem constants: B=32, Cin=11, H=W=128, K=8, P=7, TN=16, ED=64, SD=32
// out: (32, 64, 128, 128) float32

// ---------------- static device scratch ----------------
__device__ __align__(256) float g_TW[12 * 9 * 64];        // tap weights per class (11 = pad = 0)
__device__ __align__(256) float g_AT[64 * 64];            // AT[k][o], A = (I+W1)@conv2_w
__device__ __align__(256) float g_D[8 * 8 * 64];          // D[hm*8+wm][o]
__device__ __align__(256) float g_Fs[10 * 10 * 12 * 64];  // [ht][wt][cc][o]
__device__ __align__(256) float g_Fr[10 * 12 * 12 * 64];  // ht==8: [wt][cc][cb][o]
__device__ __align__(256) float g_Fc[10 * 12 * 12 * 64];  // wt==8: [ht][cc][cr][o]
__device__ __align__(256) float g_corner[32 * 225 * 64];  // [b][ti][tj][o]
__device__ int   g_lab[32 * 16 * 16];

// row kinds per position type t (0..9): 0=PAD,1=ZERO,2=CUR,3=NEXT
__constant__ int c_rk[10][3] = {
    {0,2,2},{1,2,2},{2,2,2},{2,2,2},{2,2,2},{2,2,2},{2,2,2},{2,2,1},{2,1,3},{2,1,0}
};

__device__ __forceinline__ int cellcls(int rk, int ck, int cc, int cr, int cb, int cd) {
    if (rk == 0 || ck == 0) return 11;
    if (rk == 1 || ck == 1) return 0;
    if (rk == 2) return (ck == 2) ? cc : cr;
    return (ck == 2) ? cb : cd;
}
__device__ __forceinline__ int hm_of(int t) { return (t <= 1) ? 0 : ((t <= 7) ? t - 1 : 7); }

// ================= K1: setup (AT / D / TW) + labels, one launch =================
// blocks 0..15: AT | 16..31: D (+prolog) | 32..58: TW | 59..90: labels
__global__ __launch_bounds__(256) void k1_kernel(
    const float* __restrict__ x,
    const float* __restrict__ c1w, const float* __restrict__ c1b,
    const float* __restrict__ c2w, const float* __restrict__ c2b,
    const float* __restrict__ sew, const float* __restrict__ seb,
    const float* __restrict__ slw, const float* __restrict__ slb,
    const float* __restrict__ rpw, const float* __restrict__ rpb,
    const float* __restrict__ fw,  const float* __restrict__ fb)
{
    __shared__ __align__(16) float smem[9600];
    int tid = threadIdx.x;
    int blk = blockIdx.x;

    if (blk < 16) {
        // ---- AT[k][o] = conv2_w[o][k] + sum_m fus_w[o][m]*conv2_w[m][k] ----
        float* sc2w = smem;          // 4096
        float* sfw4 = smem + 4096;   // 512: 4 fw rows
        int o0 = blk * 4;
        {
            const float4* src = (const float4*)c2w;
            float4* dst = (float4*)sc2w;
            #pragma unroll
            for (int i = 0; i < 4; i++) dst[i * 256 + tid] = src[i * 256 + tid];
            if (tid < 128) ((float4*)sfw4)[tid] = ((const float4*)(fw + o0 * 128))[tid];
        }
        __syncthreads();
        int ol = tid >> 6, k = tid & 63;
        int o = o0 + ol;
        float a0 = sc2w[o * 64 + k], a1 = 0.f, a2 = 0.f, a3 = 0.f;
        #pragma unroll
        for (int m = 0; m < 64; m += 4) {
            a0 += sfw4[ol * 128 + m + 0] * sc2w[(m + 0) * 64 + k];
            a1 += sfw4[ol * 128 + m + 1] * sc2w[(m + 1) * 64 + k];
            a2 += sfw4[ol * 128 + m + 2] * sc2w[(m + 2) * 64 + k];
            a3 += sfw4[ol * 128 + m + 3] * sc2w[(m + 3) * 64 + k];
        }
        g_AT[k * 64 + o] = (a0 + a1) + (a2 + a3);
    } else if (blk < 32) {
        // ---- D with staged fw (pitch 129) + parallel prolog ----
        float* sfw  = smem;                 // 8256
        float* sh_h = smem + 8256;          // 784
        float* sh_p = sh_h + 784;           // 256
        float* sh_sv = sh_p + 256;          // 32
        float* sc2b = sh_sv + 32;           // 64
        float* srpb = sc2b + 64;            // 32
        float* srpw = srpb + 32;            // 64

        {
            const float4* fw4 = (const float4*)fw;
            #pragma unroll
            for (int it = 0; it < 8; it++) {
                int f = it * 256 + tid;
                float4 v = fw4[f];
                int o = f >> 5, j4 = (f & 31) * 4;
                float* d = sfw + o * 129 + j4;
                d[0] = v.x; d[1] = v.y; d[2] = v.z; d[3] = v.w;
            }
        }
        for (int idx = tid; idx < 784; idx += 256) {
            int c = idx / 49, r = (idx % 49) / 7, j = idx % 7;
            float v = seb[c];
            #pragma unroll
            for (int ky = 0; ky < 3; ky++)
                #pragma unroll
                for (int kx = 0; kx < 3; kx++) {
                    int rr = r - 1 + ky, ccol = j - 1 + kx;
                    if (rr >= 0 && rr < 7 && ccol >= 0 && ccol < 7) v += sew[c * 9 + ky * 3 + kx];
                }
            sh_h[idx] = fmaxf(v, 0.f);
        }
        if (tid < 64) sc2b[tid] = c2b[tid];
        if (tid < 32) srpb[tid] = rpb[tid];
        if (tid < 64) srpw[tid] = rpw[tid];
        __syncthreads();
        {   // adaptive maxpool 7->4
            int c = tid / 16, ri = (tid % 16) / 4, rj = tid % 4;
            const int s4[4] = {0, 1, 3, 5}, e4[4] = {2, 4, 6, 7};
            float m = -1e30f;
            for (int r = s4[ri]; r < e4[ri]; r++)
                for (int cc = s4[rj]; cc < e4[rj]; cc++)
                    m = fmaxf(m, sh_h[c * 49 + r * 7 + cc]);
            sh_p[tid] = m;
        }
        __syncthreads();
        {   // shape_vec: warp w handles rows s = 4w..4w+3
            int warp = tid >> 5, lane = tid & 31;
            const float4* p4 = (const float4*)sh_p;
            float4 pa = p4[lane], pb = p4[lane + 32];
            #pragma unroll
            for (int si = 0; si < 4; si++) {
                int s = warp * 4 + si;
                const float4* row = (const float4*)(slw + s * 256);
                float4 ra = row[lane], rb = row[lane + 32];
                float part = ra.x * pa.x + ra.y * pa.y + ra.z * pa.z + ra.w * pa.w
                           + rb.x * pb.x + rb.y * pb.y + rb.z * pb.z + rb.w * pb.w;
                #pragma unroll
                for (int off = 16; off > 0; off >>= 1)
                    part += __shfl_down_sync(0xffffffffu, part, off);
                if (lane == 0) sh_sv[s] = fmaxf(part + slb[s], 0.f);
            }
        }
        __syncthreads();
        int p = (blk - 16) * 256 + tid;  // < 4096
        int hw = p >> 6, o = p & 63, hm = hw >> 3, wm = hw & 7;
        float d0 = sc2b[o] + fb[o], d1 = 0.f, d2 = 0.f, d3 = 0.f;
        #pragma unroll
        for (int m = 0; m < 64; m += 4) {
            d0 += sfw[o * 129 + m + 0] * sc2b[m + 0];
            d1 += sfw[o * 129 + m + 1] * sc2b[m + 1];
            d2 += sfw[o * 129 + m + 2] * sc2b[m + 2];
            d3 += sfw[o * 129 + m + 3] * sc2b[m + 3];
        }
        if (hm < 7 && wm < 7) {
            float fi = hm * (1.0f / 6.0f), fj = wm * (1.0f / 6.0f);
            #pragma unroll
            for (int s = 0; s < 32; s += 2) {
                d0 += sfw[o * 129 + 64 + s] * sh_sv[s];
                d1 += sfw[o * 129 + 65 + s] * sh_sv[s + 1];
            }
            #pragma unroll
            for (int s = 0; s < 32; s += 2) {
                d2 += sfw[o * 129 + 96 + s] * (srpb[s] + srpw[2 * s] * fi + srpw[2 * s + 1] * fj);
                d3 += sfw[o * 129 + 97 + s] * (srpb[s + 1] + srpw[2 * s + 2] * fi + srpw[2 * s + 3] * fj);
            }
        }
        g_D[hw * 64 + o] = (d0 + d1) + (d2 + d3);
    } else if (blk < 59) {
        // ---- TW[class][tap][o] ----
        int idx = (blk - 32) * 256 + tid;
        if (idx < 12 * 9 * 64) {
            int c = idx / (9 * 64), t = (idx / 64) % 9, o = idx & 63;
            g_TW[idx] = (c < 11) ? c1w[o * 99 + c * 9 + t] : 0.f;
        }
    } else {
        // ---- labels: argmax over 11 one-hot channels at tile origin ----
        int idx = (blk - 59) * 256 + tid;  // < 8192
        int b = idx >> 8, ty = (idx >> 4) & 15, tx = idx & 15;
        const float* px = x + (long long)b * 11 * 16384 + (ty * 8) * 128 + (tx * 8);
        float v[11];
        #pragma unroll
        for (int c = 0; c < 11; c++) v[c] = px[(long long)c * 16384];
        int best = 0; float bv = v[0];
        #pragma unroll
        for (int c = 1; c < 11; c++) { if (v[c] > bv) { bv = v[c]; best = c; } }
        g_lab[idx] = best;
    }
}

// ================= K2: tables + corners (corners -> g_corner) =================
// blocks 0..111: table entries (3564), blocks 112..336: corner entries (7200)
__global__ __launch_bounds__(256) void k2_kernel(const float* __restrict__ c1b) {
    __shared__ float sAT[64 * 64];
    __shared__ float sy[4][64];
    int tid = threadIdx.x;
    {
        const float4* src = (const float4*)g_AT;
        float4* dst4 = (float4*)sAT;
        #pragma unroll
        for (int i = 0; i < 4; i++) dst4[i * 256 + tid] = src[i * 256 + tid];
    }
    __syncthreads();

    int el = tid >> 6, o = tid & 63;
    float bias = c1b[o];

    if (blockIdx.x < 112) {
        #pragma unroll 1
        for (int it = 0; it < 8; it++) {
            int e = blockIdx.x * 32 + it * 4 + el;
            int ht = 0, wt = 0, cc = 0, cr = 11, cb = 11;
            float* dst = nullptr;
            bool valid = (e < 3564);
            if (valid) {
                if (e < 972) {
                    cc = e % 12; int r = e / 12;
                    int wi = r % 9, hi = r / 9;
                    wt = (wi == 8) ? 9 : wi;
                    ht = (hi == 8) ? 9 : hi;
                    dst = &g_Fs[((ht * 10 + wt) * 12 + cc) * 64];
                } else if (e < 972 + 1296) {
                    int r = e - 972;
                    cb = r % 12; r /= 12; cc = r % 12;
                    int wi = r / 12; wt = (wi == 8) ? 9 : wi; ht = 8;
                    dst = &g_Fr[((wt * 12 + cc) * 12 + cb) * 64];
                } else {
                    int r = e - 972 - 1296;
                    cr = r % 12; r /= 12; cc = r % 12;
                    int hi = r / 12; ht = (hi == 8) ? 9 : hi; wt = 8;
                    dst = &g_Fc[((ht * 12 + cc) * 12 + cr) * 64];
                }
                float y = bias;
                #pragma unroll
                for (int dy = 0; dy < 3; dy++)
                    #pragma unroll
                    for (int dx = 0; dx < 3; dx++) {
                        int rk = c_rk[ht][dy], ck = c_rk[wt][dx];
                        int cls = cellcls(rk, ck, cc, cr, cb, 11);
                        y += g_TW[(cls * 9 + dy * 3 + dx) * 64 + o];
                    }
                sy[el][o] = fmaxf(y, 0.f);
            }
            __syncthreads();
            if (valid) {
                int hm = hm_of(ht), wm = hm_of(wt);
                float a0 = g_D[(hm * 8 + wm) * 64 + o], a1 = 0.f, a2 = 0.f, a3 = 0.f;
                #pragma unroll
                for (int k = 0; k < 64; k += 4) {
                    a0 += sAT[(k + 0) * 64 + o] * sy[el][k + 0];
                    a1 += sAT[(k + 1) * 64 + o] * sy[el][k + 1];
                    a2 += sAT[(k + 2) * 64 + o] * sy[el][k + 2];
                    a3 += sAT[(k + 3) * 64 + o] * sy[el][k + 3];
                }
                dst[o] = (a0 + a1) + (a2 + a3);
            }
            __syncthreads();
        }
    } else {
        #pragma unroll 1
        for (int it = 0; it < 8; it++) {
            int e = (blockIdx.x - 112) * 32 + it * 4 + el;  // < 7200 exactly
            int b = e / 225, r = e % 225, ti = r / 15, tj = r % 15;
            int labbase = (b << 8) + (ti << 4) + tj;
            int cc = g_lab[labbase], cr = g_lab[labbase + 1];
            int cb = g_lab[labbase + 16], cd = g_lab[labbase + 17];
            float y = bias;
            #pragma unroll
            for (int dy = 0; dy < 3; dy++)
                #pragma unroll
                for (int dx = 0; dx < 3; dx++) {
                    int rk = c_rk[8][dy], ck = c_rk[8][dx];
                    int cls = cellcls(rk, ck, cc, cr, cb, cd);
                    y += g_TW[(cls * 9 + dy * 3 + dx) * 64 + o];
                }
            sy[el][o] = fmaxf(y, 0.f);
            __syncthreads();
            float a0 = g_D[(7 * 8 + 7) * 64 + o], a1 = 0.f, a2 = 0.f, a3 = 0.f;
            #pragma unroll
            for (int k = 0; k < 64; k += 4) {
                a0 += sAT[(k + 0) * 64 + o] * sy[el][k + 0];
                a1 += sAT[(k + 1) * 64 + o] * sy[el][k + 1];
                a2 += sAT[(k + 2) * 64 + o] * sy[el][k + 2];
                a3 += sAT[(k + 3) * 64 + o] * sy[el][k + 3];
            }
            g_corner[e * 64 + o] = (a0 + a1) + (a2 + a3);
            __syncthreads();
        }
    }
}

// ================= K3: main — 8-lane gather (full-line LDG), pitch-129 transpose =================
// block = one (b,h) image row; 256 threads; 4 passes of 32 pixels.
// Warp = 4 pixels x 8 lanes: lane l8 loads F[l8] and F[l8+8] (two full 128B lines / 4 px).
__global__ __launch_bounds__(256) void main_kernel(float* __restrict__ out) {
    __shared__ float s[64 * 129];   // [ch][w], pitch 129 (odd -> conflict-free)
    int tid = threadIdx.x;
    int bh = blockIdx.x;
    int b = bh >> 7, h = bh & 127;
    int hm = h & 7;
    int ht = (hm == 0) ? (h == 0 ? 0 : 1) : (hm < 7 ? hm + 1 : (h == 127 ? 9 : 8));
    int ty = h >> 3;
    int labrow = (b << 8) + (ty << 4);
    int px32 = tid >> 3;        // 0..31: pixel within pass
    int l8 = tid & 7;           // lane within pixel
    int ch = 4 * l8;

    #pragma unroll
    for (int pass = 0; pass < 4; pass++) {
        int w = pass * 32 + px32;
        int wm = w & 7;
        int wt = (wm == 0) ? (w == 0 ? 0 : 1) : (wm < 7 ? wm + 1 : (w == 127 ? 9 : 8));
        int tx = w >> 3;
        int cc = g_lab[labrow + tx];
        const float4* F;
        if (ht == 8) {      // uniform per block
            if (wt == 8) {
                F = (const float4*)&g_corner[((b * 15 + ty) * 15 + tx) * 64];
            } else {
                int cb = g_lab[labrow + tx + 16];
                F = (const float4*)&g_Fr[((wt * 12 + cc) * 12 + cb) * 64];
            }
        } else {
            if (wt == 8) {
                int cr = g_lab[labrow + tx + 1];
                F = (const float4*)&g_Fc[((ht * 12 + cc) * 12 + cr) * 64];
            } else {
                F = (const float4*)&g_Fs[((ht * 10 + wt) * 12 + cc) * 64];
            }
        }
        float4 va = F[l8];       // line A of row
        float4 vb = F[l8 + 8];   // line B of row
        s[(ch + 0) * 129 + w] = va.x;
        s[(ch + 1) * 129 + w] = va.y;
        s[(ch + 2) * 129 + w] = va.z;
        s[(ch + 3) * 129 + w] = va.w;
        s[(ch + 32) * 129 + w] = vb.x;
        s[(ch + 33) * 129 + w] = vb.y;
        s[(ch + 34) * 129 + w] = vb.z;
        s[(ch + 35) * 129 + w] = vb.w;
    }
    __syncthreads();

    // store: idx = it*256 + tid -> c = idx>>7, w = idx&127; warp = 32 consecutive w of one c
    float* obase = out + ((long long)b << 20) + h * 128;
    #pragma unroll
    for (int it = 0; it < 32; it++) {
        int idx = it * 256 + tid;
        int c = idx >> 7, w = idx & 127;
        obase[c * 16384 + w] = s[c * 129 + w];
    }
}

// ---------------- launch ----------------
extern "C" void kernel_launch(void* const* d_in, const int* in_sizes, int n_in,
                              void* d_out, int out_size) {
    const float* x   = (const float*)d_in[0];
    const float* c1w = (const float*)d_in[1];
    const float* c1b = (const float*)d_in[2];
    const float* c2w = (const float*)d_in[3];
    const float* c2b = (const float*)d_in[4];
    const float* sew = (const float*)d_in[5];
    const float* seb = (const float*)d_in[6];
    const float* slw = (const float*)d_in[7];
    const float* slb = (const float*)d_in[8];
    const float* rpw = (const float*)d_in[9];
    const float* rpb = (const float*)d_in[10];
    const float* fus_w = (const float*)d_in[11];
    const float* fus_b = (const float*)d_in[12];
    float* out = (float*)d_out;

    k1_kernel<<<91, 256>>>(x, c1w, c1b, c2w, c2b, sew, seb, slw, slb, rpw, rpb, fus_w, fus_b);
    k2_kernel<<<337, 256>>>(c1b);
    main_kernel<<<4096, 256>>>(out);
}